// round 1
// baseline (speedup 1.0000x reference)
#include <cuda_runtime.h>
#include <cuda_bf16.h>
#include <cstdint>

#define BATCH 4
#define NTOK  4096
#define CIN   128
#define FDIM  256
#define MTOT  (BATCH*NTOK)   // 16384

// ---------------- scratch (device globals; no allocation allowed) ----------
__device__ float          g_x [MTOT*FDIM];   // fp32 x for residual (16.8 MB)
__device__ __nv_bfloat16  g_xb[MTOT*FDIM];   // bf16 x for QKV GEMM  (8.4 MB)
__device__ __nv_bfloat16  g_q [MTOT*FDIM];
__device__ __nv_bfloat16  g_k [MTOT*FDIM];
__device__ __nv_bfloat16  g_v [MTOT*FDIM];

// ---------------- helpers ---------------------------------------------------
static __device__ __forceinline__ uint32_t smem_u32(const void* p) {
    return (uint32_t)__cvta_generic_to_shared(p);
}
static __device__ __forceinline__ void ldmx4(uint32_t& r0, uint32_t& r1,
                                             uint32_t& r2, uint32_t& r3, uint32_t addr) {
    asm volatile("ldmatrix.sync.aligned.m8n8.x4.shared.b16 {%0,%1,%2,%3}, [%4];"
                 : "=r"(r0), "=r"(r1), "=r"(r2), "=r"(r3) : "r"(addr));
}
static __device__ __forceinline__ void ldmx4t(uint32_t& r0, uint32_t& r1,
                                              uint32_t& r2, uint32_t& r3, uint32_t addr) {
    asm volatile("ldmatrix.sync.aligned.m8n8.x4.trans.shared.b16 {%0,%1,%2,%3}, [%4];"
                 : "=r"(r0), "=r"(r1), "=r"(r2), "=r"(r3) : "r"(addr));
}
static __device__ __forceinline__ void mma_bf16(float* c, const uint32_t* a,
                                                uint32_t b0, uint32_t b1) {
    asm volatile("mma.sync.aligned.m16n8k16.row.col.f32.bf16.bf16.f32 "
                 "{%0,%1,%2,%3}, {%4,%5,%6,%7}, {%8,%9}, {%0,%1,%2,%3};"
                 : "+f"(c[0]), "+f"(c[1]), "+f"(c[2]), "+f"(c[3])
                 : "r"(a[0]), "r"(a[1]), "r"(a[2]), "r"(a[3]), "r"(b0), "r"(b1));
}
// pack two f32 -> bf16x2 register, 'lo' in low 16 bits (even k), 'hi' in high.
static __device__ __forceinline__ uint32_t pack_bf16x2(float lo, float hi) {
    uint32_t d;
    asm("cvt.rn.bf16x2.f32 %0, %1, %2;" : "=r"(d) : "f"(hi), "f"(lo));
    return d;
}

// ---------------- kernel 1: x = inputs @ W_proj + b_proj (fp32) -------------
// C[16384,256] = A[16384,128] @ W[128,256]; writes fp32 + bf16 copies.
__global__ void __launch_bounds__(256) proj_kernel(const float* __restrict__ A,
                                                   const float* __restrict__ W,
                                                   const float* __restrict__ bias) {
    __shared__ __align__(16) float As[16][68];  // [k][m], padded
    __shared__ __align__(16) float Bs[16][68];  // [k][n], padded
    const int m0 = blockIdx.x * 64, n0 = blockIdx.y * 64;
    const int tx = threadIdx.x & 15, ty = threadIdx.x >> 4;

    float c[4][4];
#pragma unroll
    for (int i = 0; i < 4; i++)
#pragma unroll
        for (int j = 0; j < 4; j++) c[i][j] = 0.f;

    for (int k0 = 0; k0 < CIN; k0 += 16) {
#pragma unroll
        for (int i = threadIdx.x; i < 1024; i += 256) {
            int m = i >> 4, k = i & 15;
            As[k][m] = A[(size_t)(m0 + m) * CIN + k0 + k];
        }
#pragma unroll
        for (int i = threadIdx.x; i < 1024; i += 256) {
            int k = i >> 6, n = i & 63;
            Bs[k][n] = W[(size_t)(k0 + k) * FDIM + n0 + n];
        }
        __syncthreads();
#pragma unroll
        for (int kk = 0; kk < 16; kk++) {
            float4 av = *(const float4*)&As[kk][ty * 4];
            float4 bv = *(const float4*)&Bs[kk][tx * 4];
            float a[4] = {av.x, av.y, av.z, av.w};
            float b[4] = {bv.x, bv.y, bv.z, bv.w};
#pragma unroll
            for (int i = 0; i < 4; i++)
#pragma unroll
                for (int j = 0; j < 4; j++) c[i][j] += a[i] * b[j];
        }
        __syncthreads();
    }
#pragma unroll
    for (int i = 0; i < 4; i++) {
        int m = m0 + ty * 4 + i;
#pragma unroll
        for (int j = 0; j < 4; j++) {
            int n = n0 + tx * 4 + j;
            float v = c[i][j] + bias[n];
            g_x [(size_t)m * FDIM + n] = v;
            g_xb[(size_t)m * FDIM + n] = __float2bfloat16(v);
        }
    }
}

// ---------------- kernel 2: Q/K/V = x @ W_{q,k,v} + b (bf16 mma) -------------
// Grid: (256, 4, 3); 128 threads (4 warps, each 16 rows x 64 cols).
__global__ void __launch_bounds__(128) qkv_kernel(const float* __restrict__ Wq,
                                                  const float* __restrict__ bq,
                                                  const float* __restrict__ Wk,
                                                  const float* __restrict__ bk,
                                                  const float* __restrict__ Wv,
                                                  const float* __restrict__ bv) {
    __shared__ __align__(16) __nv_bfloat16 sA[64][72];  // [m][k], padded (+8)
    __shared__ __align__(16) __nv_bfloat16 sW[64][72];  // [k][g], padded (+8)
    const int m0 = blockIdx.x * 64, n0 = blockIdx.y * 64;
    const float* W;  const float* bias;  __nv_bfloat16* out;
    if (blockIdx.z == 0)      { W = Wq; bias = bq; out = g_q; }
    else if (blockIdx.z == 1) { W = Wk; bias = bk; out = g_k; }
    else                      { W = Wv; bias = bv; out = g_v; }

    const int tid = threadIdx.x, warp = tid >> 5, lane = tid & 31;

    float o[8][4];
#pragma unroll
    for (int j = 0; j < 8; j++)
#pragma unroll
        for (int r = 0; r < 4; r++) o[j][r] = 0.f;

    const uint32_t a_addr0 = smem_u32(&sA[warp * 16 + (lane & 15)][(lane & 16) >> 1]);
    const uint32_t b_addr0 = smem_u32(&sW[(lane & 7) + (lane & 8)][(lane & 16) >> 1]);

    for (int k0 = 0; k0 < FDIM; k0 += 64) {
        __syncthreads();
#pragma unroll
        for (int i = tid; i < 512; i += 128) {   // A tile: 64x64 bf16
            int r = i >> 3, c8 = i & 7;
            *(uint4*)&sA[r][c8 * 8] =
                *(const uint4*)&g_xb[(size_t)(m0 + r) * FDIM + k0 + c8 * 8];
        }
#pragma unroll
        for (int i = tid; i < 1024; i += 128) {  // W tile: 64x64 f32 -> bf16
            int r = i >> 4, c4 = i & 15;
            float4 w = *(const float4*)&W[(size_t)(k0 + r) * FDIM + n0 + c4 * 4];
            *(__nv_bfloat162*)&sW[r][c4 * 4]     = __floats2bfloat162_rn(w.x, w.y);
            *(__nv_bfloat162*)&sW[r][c4 * 4 + 2] = __floats2bfloat162_rn(w.z, w.w);
        }
        __syncthreads();
#pragma unroll
        for (int kc = 0; kc < 4; kc++) {
            uint32_t a[4];
            ldmx4(a[0], a[1], a[2], a[3], a_addr0 + kc * 16 * 2);
#pragma unroll
            for (int np = 0; np < 4; np++) {
                uint32_t b0, b1, b2, b3;
                ldmx4t(b0, b1, b2, b3,
                       b_addr0 + (uint32_t)(kc * 16 * 72 + np * 16) * 2);
                mma_bf16(o[2 * np],     a, b0, b1);
                mma_bf16(o[2 * np + 1], a, b2, b3);
            }
        }
    }
    const int g = lane >> 2, qd = lane & 3;
    const int row = m0 + warp * 16 + g;
#pragma unroll
    for (int j = 0; j < 8; j++) {
        int col = n0 + j * 8 + qd * 2;
        float bf0 = bias[col], bf1 = bias[col + 1];
        *(__nv_bfloat162*)&out[(size_t)row * FDIM + col] =
            __floats2bfloat162_rn(o[j][0] + bf0, o[j][1] + bf1);
        *(__nv_bfloat162*)&out[(size_t)(row + 8) * FDIM + col] =
            __floats2bfloat162_rn(o[j][2] + bf0, o[j][3] + bf1);
    }
}

// ---------------- kernel 3: flash attention + residual ----------------------
// Grid: (64, 4); 128 threads. BM=64 q-rows/block (16/warp), BN=64 keys/iter.
// SMEM rows padded to 264 bf16 (528B, shifts 16B/row -> conflict-free ldmatrix).
#define SROW 264
#define ATT_SMEM (3 * 64 * SROW * 2)

__global__ void __launch_bounds__(128) attn_kernel(float* __restrict__ out,
                                                   const float* __restrict__ gamma_p) {
    extern __shared__ __nv_bfloat16 smem[];
    __nv_bfloat16* sQ = smem;
    __nv_bfloat16* sK = smem + 64 * SROW;
    __nv_bfloat16* sV = smem + 2 * 64 * SROW;

    const int batch = blockIdx.y, mt = blockIdx.x;
    const int tid = threadIdx.x, warp = tid >> 5, lane = tid & 31;
    const int g = lane >> 2, qd = lane & 3;

    const __nv_bfloat16* Qg = g_q + ((size_t)batch * NTOK + mt * 64) * FDIM;
#pragma unroll
    for (int i = tid; i < 2048; i += 128) {
        int r = i >> 5, c8 = i & 31;
        *(uint4*)&sQ[r * SROW + c8 * 8] = *(const uint4*)&Qg[(size_t)r * FDIM + c8 * 8];
    }

    float o[32][4];
#pragma unroll
    for (int j = 0; j < 32; j++)
#pragma unroll
        for (int r = 0; r < 4; r++) o[j][r] = 0.f;
    float m0 = -1e30f, m1 = -1e30f, l0 = 0.f, l1 = 0.f;

    // fragment base addresses (verified layouts):
    // Q (A, non-trans): row = wbase + (l&15), d-off = (l&16)>>1
    const uint32_t qaddr = smem_u32(sQ) +
        (uint32_t)(((warp * 16 + (lane & 15)) * SROW + ((lane & 16) >> 1)) * 2);
    // K (B, non-trans): row = n0 + (l&7) + ((l&16)>>1? no: +8 if l&16), d-off = (l&8)
    const uint32_t kaddr = smem_u32(sK) +
        (uint32_t)((((lane & 7) + ((lane & 16) >> 1)) * SROW + (lane & 8)) * 2);
    // V (B, trans): row = kbase + (l&7) + (l&8), d-off = (l&16)>>1
    const uint32_t vaddr = smem_u32(sV) +
        (uint32_t)((((lane & 7) + (lane & 8)) * SROW + ((lane & 16) >> 1)) * 2);

    for (int kt = 0; kt < 64; kt++) {
        const __nv_bfloat16* Kg = g_k + ((size_t)batch * NTOK + kt * 64) * FDIM;
        const __nv_bfloat16* Vg = g_v + ((size_t)batch * NTOK + kt * 64) * FDIM;
        __syncthreads();
#pragma unroll
        for (int i = tid; i < 2048; i += 128) {
            int r = i >> 5, c8 = i & 31;
            *(uint4*)&sK[r * SROW + c8 * 8] = *(const uint4*)&Kg[(size_t)r * FDIM + c8 * 8];
            *(uint4*)&sV[r * SROW + c8 * 8] = *(const uint4*)&Vg[(size_t)r * FDIM + c8 * 8];
        }
        __syncthreads();

        // ---- S = Q K^T (16 x 64 per warp) ----
        float s[8][4];
#pragma unroll
        for (int j = 0; j < 8; j++)
#pragma unroll
            for (int r = 0; r < 4; r++) s[j][r] = 0.f;

#pragma unroll 4
        for (int kc = 0; kc < 16; kc++) {
            uint32_t a[4];
            ldmx4(a[0], a[1], a[2], a[3], qaddr + (uint32_t)(kc * 16 * 2));
#pragma unroll
            for (int np = 0; np < 4; np++) {
                uint32_t b0, b1, b2, b3;
                ldmx4(b0, b1, b2, b3,
                      kaddr + (uint32_t)((np * 16 * SROW + kc * 16) * 2));
                mma_bf16(s[2 * np],     a, b0, b1);
                mma_bf16(s[2 * np + 1], a, b2, b3);
            }
        }

        // ---- online softmax (no 1/sqrt(d) scale in reference) ----
        float mx0 = -1e30f, mx1 = -1e30f;
#pragma unroll
        for (int j = 0; j < 8; j++) {
            mx0 = fmaxf(mx0, fmaxf(s[j][0], s[j][1]));
            mx1 = fmaxf(mx1, fmaxf(s[j][2], s[j][3]));
        }
        mx0 = fmaxf(mx0, __shfl_xor_sync(0xffffffffu, mx0, 1));
        mx0 = fmaxf(mx0, __shfl_xor_sync(0xffffffffu, mx0, 2));
        mx1 = fmaxf(mx1, __shfl_xor_sync(0xffffffffu, mx1, 1));
        mx1 = fmaxf(mx1, __shfl_xor_sync(0xffffffffu, mx1, 2));
        float mn0 = fmaxf(m0, mx0), mn1 = fmaxf(m1, mx1);
        float al0 = __expf(m0 - mn0), al1 = __expf(m1 - mn1);
        m0 = mn0; m1 = mn1;

        float sum0 = 0.f, sum1 = 0.f;
#pragma unroll
        for (int j = 0; j < 8; j++) {
            s[j][0] = __expf(s[j][0] - mn0);
            s[j][1] = __expf(s[j][1] - mn0);
            s[j][2] = __expf(s[j][2] - mn1);
            s[j][3] = __expf(s[j][3] - mn1);
            sum0 += s[j][0] + s[j][1];
            sum1 += s[j][2] + s[j][3];
        }
        sum0 += __shfl_xor_sync(0xffffffffu, sum0, 1);
        sum0 += __shfl_xor_sync(0xffffffffu, sum0, 2);
        sum1 += __shfl_xor_sync(0xffffffffu, sum1, 1);
        sum1 += __shfl_xor_sync(0xffffffffu, sum1, 2);
        l0 = l0 * al0 + sum0;
        l1 = l1 * al1 + sum1;

#pragma unroll
        for (int j = 0; j < 32; j++) {
            o[j][0] *= al0; o[j][1] *= al0; o[j][2] *= al1; o[j][3] *= al1;
        }

        // ---- P (C-layout) -> A-fragments, in-register ----
        uint32_t pa[4][4];
#pragma unroll
        for (int t = 0; t < 4; t++) {
            pa[t][0] = pack_bf16x2(s[2 * t][0],     s[2 * t][1]);
            pa[t][1] = pack_bf16x2(s[2 * t][2],     s[2 * t][3]);
            pa[t][2] = pack_bf16x2(s[2 * t + 1][0], s[2 * t + 1][1]);
            pa[t][3] = pack_bf16x2(s[2 * t + 1][2], s[2 * t + 1][3]);
        }

        // ---- O += P V ----
#pragma unroll
        for (int t = 0; t < 4; t++) {
#pragma unroll
            for (int dp = 0; dp < 16; dp++) {
                uint32_t v0, v1, v2, v3;
                ldmx4t(v0, v1, v2, v3,
                       vaddr + (uint32_t)((t * 16 * SROW + dp * 16) * 2));
                mma_bf16(o[2 * dp],     pa[t], v0, v1);
                mma_bf16(o[2 * dp + 1], pa[t], v2, v3);
            }
        }
    }

    // ---- epilogue: out = gamma * O/l + x ----
    const float gamma = __ldg(gamma_p);
    const float inv0 = 1.f / l0, inv1 = 1.f / l1;
    const size_t rowbase = ((size_t)batch * NTOK + mt * 64 + warp * 16 + g) * FDIM;
    const float* xr = g_x + rowbase;
    float* orow = out + rowbase;
#pragma unroll
    for (int j = 0; j < 32; j++) {
        int col = j * 8 + qd * 2;
        orow[col]              = gamma * o[j][0] * inv0 + xr[col];
        orow[col + 1]          = gamma * o[j][1] * inv0 + xr[col + 1];
        orow[8 * FDIM + col]     = gamma * o[j][2] * inv1 + xr[8 * FDIM + col];
        orow[8 * FDIM + col + 1] = gamma * o[j][3] * inv1 + xr[8 * FDIM + col + 1];
    }
}

// ---------------- launch -----------------------------------------------------
extern "C" void kernel_launch(void* const* d_in, const int* in_sizes, int n_in,
                              void* d_out, int out_size) {
    (void)in_sizes; (void)n_in; (void)out_size;
    const float* inputs = (const float*)d_in[0];
    const float* W_proj = (const float*)d_in[1];
    const float* b_proj = (const float*)d_in[2];
    const float* W_q    = (const float*)d_in[3];
    const float* b_q    = (const float*)d_in[4];
    const float* W_k    = (const float*)d_in[5];
    const float* b_k    = (const float*)d_in[6];
    const float* W_v    = (const float*)d_in[7];
    const float* b_v    = (const float*)d_in[8];
    const float* gamma  = (const float*)d_in[9];
    float* out = (float*)d_out;

    cudaFuncSetAttribute(attn_kernel, cudaFuncAttributeMaxDynamicSharedMemorySize,
                         ATT_SMEM);

    proj_kernel<<<dim3(MTOT / 64, FDIM / 64), 256>>>(inputs, W_proj, b_proj);
    qkv_kernel<<<dim3(MTOT / 64, FDIM / 64, 3), 128>>>(W_q, b_q, W_k, b_k, W_v, b_v);
    attn_kernel<<<dim3(NTOK / 64, BATCH), 128, ATT_SMEM>>>(out, gamma);
}